// round 7
// baseline (speedup 1.0000x reference)
#include <cuda_runtime.h>
#include <cuda_bf16.h>
#include <cstdint>
#include <float.h>

#define N_VEC    32768
#define DIMS     256
#define KCODES   1024
#define MARGIN   0.05f

// -------- device scratch ----------------------------------------------------
__device__ __align__(16) float          g_eT[KCODES * DIMS];    // fp32 codes [K][D]
__device__ __align__(16) __nv_bfloat16  g_etb[KCODES * DIMS];   // bf16 codes [K][D]
__device__ float  g_enorm2[KCODES];
__device__ double g_loss;

// -------- common helpers ------------------------------------------------------
__device__ __forceinline__ uint32_t smem_u32(const void* p) {
    uint32_t a;
    asm("{ .reg .u64 t; cvta.to.shared.u64 t, %1; cvt.u32.u64 %0, t; }"
        : "=r"(a) : "l"(p));
    return a;
}
__device__ __forceinline__ unsigned pack_bf2(float a, float b) {
    __nv_bfloat162 h = __floats2bfloat162_rn(a, b);
    return *reinterpret_cast<unsigned*>(&h);
}
__device__ __forceinline__ bool better(float v, int k, float v2, int k2) {
    return (v < v2) || (v == v2 && k < k2);
}
__device__ __forceinline__ void merge_top2(float& v1, int& k1, float& v2, int& k2,
                                           float ov1, int ok1, float ov2, int ok2) {
    float m1v, m2v; int m1k, m2k;
    if (better(v1, k1, ov1, ok1)) {
        m1v = v1; m1k = k1;
        if (better(v2, k2, ov1, ok1)) { m2v = v2; m2k = k2; }
        else                          { m2v = ov1; m2k = ok1; }
    } else {
        m1v = ov1; m1k = ok1;
        if (better(ov2, ok2, v1, k1)) { m2v = ov2; m2k = ok2; }
        else                          { m2v = v1;  m2k = k1;  }
    }
    v1 = m1v; k1 = m1k; v2 = m2v; k2 = m2k;
}

// reference-rounding-emulation tie vote (identical to the rel_err=0 round-2 code)
__device__ int vote_tie(const float* __restrict__ x, int v, int ka, int kb) {
    const float* xr = x + (size_t)v * DIMS;
    const float* ea = g_eT + (size_t)ka * DIMS;
    const float* eb = g_eT + (size_t)kb * DIMS;
    double sA = 0.0, sBa = 0.0, sBb = 0.0;
    for (int d = 0; d < DIMS; d++) {
        double xv = (double)xr[d];
        sA  += xv * xv;
        sBa += xv * (double)ea[d];
        sBb += xv * (double)eb[d];
    }
    float Ba = (float)sBa, Bb = (float)sBb;
    float Ca = g_enorm2[ka], Cb = g_enorm2[kb];
    int ab = __float_as_int((float)sA);
    int votes = 0;
#pragma unroll
    for (int jj = -2; jj <= 2; jj++) {
        int w = 3 - (jj < 0 ? -jj : jj);
        float Aj = __int_as_float(ab + jj);
        float da = __fadd_rn(__fsub_rn(Aj, __fmul_rn(2.f, Ba)), Ca);
        float db = __fadd_rn(__fsub_rn(Aj, __fmul_rn(2.f, Bb)), Cb);
        if (da <= db) votes += w;
    }
    return (votes >= 5) ? ka : kb;
}

__device__ __forceinline__ float exact_score(const float4* xr, int k, float enk) {
    const float4* er = (const float4*)(g_eT + (size_t)k * DIMS);
    float a0 = 0.f, a1 = 0.f, a2 = 0.f, a3 = 0.f;
#pragma unroll 8
    for (int d4 = 0; d4 < DIMS / 4; d4++) {
        float4 xv = __ldg(xr + d4), ev = __ldg(er + d4);
        a0 = fmaf(xv.x, ev.x, a0); a1 = fmaf(xv.y, ev.y, a1);
        a2 = fmaf(xv.z, ev.z, a2); a3 = fmaf(xv.w, ev.w, a3);
    }
    return fmaf(-2.f, (a0 + a1) + (a2 + a3), enk);
}

// -------- pre-kernels ---------------------------------------------------------
__global__ void transpose_e_kernel(const float* __restrict__ e) {
    __shared__ float tile[32][33];
    int k0 = blockIdx.x * 32, d0 = blockIdx.y * 32;
    int tx = threadIdx.x, ty = threadIdx.y;
#pragma unroll
    for (int i = ty; i < 32; i += 8)
        tile[i][tx] = e[(size_t)(d0 + i) * KCODES + k0 + tx];
    __syncthreads();
#pragma unroll
    for (int j = ty; j < 32; j += 8)
        g_eT[(size_t)(k0 + j) * DIMS + d0 + tx] = tile[tx][j];
}

__global__ void enorm_kernel() {
    int k = blockIdx.x * 8 + (threadIdx.x >> 5);
    int lane = threadIdx.x & 31;
    const float* row = g_eT + (size_t)k * DIMS;
    double s = 0.0;
#pragma unroll
    for (int j = 0; j < 8; j++) {
        double v = (double)row[lane + 32 * j];
        s += v * v;
    }
#pragma unroll
    for (int off = 16; off; off >>= 1)
        s += __shfl_xor_sync(0xffffffffu, s, off);
    if (lane == 0) g_enorm2[k] = (float)s;
    if (blockIdx.x == 0 && threadIdx.x == 0) g_loss = 0.0;
}

__global__ void convert_etb_kernel() {
    int i = blockIdx.x * 256 + threadIdx.x;
    const float4* s = (const float4*)g_eT;
    float4 f0 = s[i * 2], f1 = s[i * 2 + 1];
    uint4 d;
    d.x = pack_bf2(f0.x, f0.y); d.y = pack_bf2(f0.z, f0.w);
    d.z = pack_bf2(f1.x, f1.y); d.w = pack_bf2(f1.z, f1.w);
    ((uint4*)g_etb)[i] = d;
}

// ============================================================================
// HMMA (mma.sync bf16) main kernel — 8 warps, 16 mma chains, screened scan
// ============================================================================
#define HT        256
#define H_MBLK    256
#define H_NCH     64
#define H_NCHUNKS 16
#define H_RSTRIDE 528                 // padded row stride (bytes) = 264 bf16
#define SMH_ENS   0
#define SMH_BIDX  4096
#define SMH_A     5120
#define SMH_B     (SMH_A + 256 * H_RSTRIDE)       // 5120 + 135168 = 140288
#define H_BUFSZ   (64 * H_RSTRIDE)                // 33792
#define SMH_TOTAL (SMH_B + 2 * H_BUFSZ)           // 207872

__device__ __forceinline__ void cp16(uint32_t dst, const void* src) {
    asm volatile("cp.async.cg.shared.global [%0], [%1], 16;"
                 :: "r"(dst), "l"(src) : "memory");
}
#define CP_COMMIT() asm volatile("cp.async.commit_group;" ::: "memory")
#define CP_WAIT1()  asm volatile("cp.async.wait_group 1;" ::: "memory")

__device__ __forceinline__ void ldsm4(uint32_t* r, uint32_t addr) {
    asm volatile("ldmatrix.sync.aligned.m8n8.x4.shared.b16 {%0,%1,%2,%3}, [%4];"
                 : "=r"(r[0]), "=r"(r[1]), "=r"(r[2]), "=r"(r[3]) : "r"(addr));
}
__device__ __forceinline__ void mma16816(float* c, const uint32_t* a,
                                         uint32_t b0, uint32_t b1) {
    asm volatile("mma.sync.aligned.m16n8k16.row.col.f32.bf16.bf16.f32 "
                 "{%0,%1,%2,%3}, {%4,%5,%6,%7}, {%8,%9}, {%0,%1,%2,%3};"
                 : "+f"(c[0]), "+f"(c[1]), "+f"(c[2]), "+f"(c[3])
                 : "r"(a[0]), "r"(a[1]), "r"(a[2]), "r"(a[3]), "r"(b0), "r"(b1));
}

__global__ void __launch_bounds__(HT, 1)
vq_hmma_kernel(const float* __restrict__ x, float* __restrict__ out) {
    extern __shared__ char smem[];
    uint32_t sb = smem_u32(smem);
    float* ens = (float*)(smem + SMH_ENS);
    int*  bidx = (int*)(smem + SMH_BIDX);
    int tid = threadIdx.x, w = tid >> 5, L = tid & 31;
    int m0 = blockIdx.x * H_MBLK;

    for (int i = tid; i < KCODES; i += HT) ens[i] = g_enorm2[i];

    // A tile: x fp32 -> bf16, padded-stride smem [256][264 bf16]
    const float4* xs = (const float4*)x;
    for (int u = tid; u < 8192; u += HT) {
        int row = u >> 5, c = u & 31;
        size_t s4 = ((size_t)(m0 + row)) * 64 + c * 2;
        float4 f0 = __ldg(xs + s4), f1 = __ldg(xs + s4 + 1);
        uint4 d;
        d.x = pack_bf2(f0.x, f0.y); d.y = pack_bf2(f0.z, f0.w);
        d.z = pack_bf2(f1.x, f1.y); d.w = pack_bf2(f1.z, f1.w);
        *(uint4*)(smem + SMH_A + row * H_RSTRIDE + c * 16) = d;
    }
    // preload B chunk 0
    {
        const char* ebase = (const char*)g_etb;
        for (int u = tid; u < 2048; u += HT)
            cp16(sb + SMH_B + (u >> 5) * H_RSTRIDE + (u & 31) * 16,
                 ebase + (size_t)(u >> 5) * 512 + (u & 31) * 16);
        CP_COMMIT();
    }

    // lane-dependent ldmatrix address parts
    uint32_t a_lane = sb + SMH_A + (uint32_t)(w * 32 + (L & 15)) * H_RSTRIDE
                    + (uint32_t)(L >> 4) * 16;
    uint32_t b_lane = (uint32_t)(L & 7) * H_RSTRIDE + (uint32_t)((L >> 3) & 1) * 16
                    + (uint32_t)(L >> 4) * (8 * H_RSTRIDE);

    // per-lane running top-3 for 4 owned rows (w*32 + {0,8,16,24} + (L>>2))
    float hv1[4], hv2[4], hv3[4]; int hk1[4], hk2[4], hk3[4];
#pragma unroll
    for (int q = 0; q < 4; q++) {
        hv1[q] = FLT_MAX; hv2[q] = FLT_MAX; hv3[q] = FLT_MAX;
        hk1[q] = 0x7fffffff; hk2[q] = 0x7fffffff; hk3[q] = 0x7fffffff;
    }

    for (int i = 0; i < H_NCHUNKS; i++) {
        if (i + 1 < H_NCHUNKS) {
            const char* ebase = (const char*)g_etb + (size_t)(i + 1) * H_NCH * 512;
            uint32_t bdst = sb + SMH_B + ((i + 1) & 1) * H_BUFSZ;
            for (int u = tid; u < 2048; u += HT)
                cp16(bdst + (u >> 5) * H_RSTRIDE + (u & 31) * 16,
                     ebase + (size_t)(u >> 5) * 512 + (u & 31) * 16);
        }
        CP_COMMIT();
        CP_WAIT1();
        __syncthreads();                       // chunk i visible; A on i==0

        uint32_t bbase = sb + SMH_B + (i & 1) * H_BUFSZ + b_lane;

        float acc[2][8][4];                    // 16 independent mma chains
#pragma unroll
        for (int t = 0; t < 2; t++)
#pragma unroll
            for (int ni = 0; ni < 8; ni++)
#pragma unroll
                for (int c = 0; c < 4; c++) acc[t][ni][c] = 0.f;

#pragma unroll 8
        for (int ks = 0; ks < 16; ks++) {
            uint32_t af0[4], af1[4];
            ldsm4(af0, a_lane + ks * 32);
            ldsm4(af1, a_lane + 16 * H_RSTRIDE + ks * 32);
#pragma unroll
            for (int p = 0; p < 4; p++) {
                uint32_t bf[4];
                ldsm4(bf, bbase + p * (16 * H_RSTRIDE) + ks * 32);
                mma16816(acc[0][2 * p],     af0, bf[0], bf[1]);
                mma16816(acc[0][2 * p + 1], af0, bf[2], bf[3]);
                mma16816(acc[1][2 * p],     af1, bf[0], bf[1]);
                mma16816(acc[1][2 * p + 1], af1, bf[2], bf[3]);
            }
        }

        // transform acc -> scores in place, then screened top-3 update
        int kb_base = i * H_NCH + (L & 3) * 2;
#pragma unroll
        for (int t = 0; t < 2; t++)
#pragma unroll
            for (int ni = 0; ni < 8; ni++) {
                int kb = kb_base + ni * 8;
                acc[t][ni][0] = fmaf(-2.f, acc[t][ni][0], ens[kb]);
                acc[t][ni][1] = fmaf(-2.f, acc[t][ni][1], ens[kb + 1]);
                acc[t][ni][2] = fmaf(-2.f, acc[t][ni][2], ens[kb]);
                acc[t][ni][3] = fmaf(-2.f, acc[t][ni][3], ens[kb + 1]);
            }

#pragma unroll
        for (int r = 0; r < 4; r++) {          // row r: acc[r>>1][*][(r&1)*2 + {0,1}]
            int t = r >> 1, cb = (r & 1) * 2;
            float m01 = fminf(fminf(acc[t][0][cb], acc[t][0][cb + 1]),
                              fminf(acc[t][1][cb], acc[t][1][cb + 1]));
            float m23 = fminf(fminf(acc[t][2][cb], acc[t][2][cb + 1]),
                              fminf(acc[t][3][cb], acc[t][3][cb + 1]));
            float m45 = fminf(fminf(acc[t][4][cb], acc[t][4][cb + 1]),
                              fminf(acc[t][5][cb], acc[t][5][cb + 1]));
            float m67 = fminf(fminf(acc[t][6][cb], acc[t][6][cb + 1]),
                              fminf(acc[t][7][cb], acc[t][7][cb + 1]));
            float rmin = fminf(fminf(m01, m23), fminf(m45, m67));
            if (rmin < hv3[r]) {               // slow path: ~3 of 16 chunks
#pragma unroll
                for (int ni = 0; ni < 8; ni++) {
#pragma unroll
                    for (int h = 0; h < 2; h++) {   // k ascending within chunk
                        float s_ = acc[t][ni][cb + h];
                        int   k_ = kb_base + ni * 8 + h;
                        if (s_ < hv3[r]) {
                            if (s_ < hv1[r]) {
                                hv3[r] = hv2[r]; hk3[r] = hk2[r];
                                hv2[r] = hv1[r]; hk2[r] = hk1[r];
                                hv1[r] = s_; hk1[r] = k_;
                            } else if (s_ < hv2[r]) {
                                hv3[r] = hv2[r]; hk3[r] = hk2[r];
                                hv2[r] = s_; hk2[r] = k_;
                            } else { hv3[r] = s_; hk3[r] = k_; }
                        }
                    }
                }
            }
        }
        __syncthreads();                       // readers done before buf reuse
    }

    // per-row decision: quad merge -> margin -> exact rescore -> tie vote
#pragma unroll 1
    for (int ri = 0; ri < 4; ri++) {
        int gr = w * 32 + ri * 8 + (L >> 2);
        float v1 = hv1[ri], v2 = hv2[ri];
        int   k1 = hk1[ri], k2 = hk2[ri];
#pragma unroll
        for (int off = 1; off <= 2; off <<= 1) {
            float ov1 = __shfl_xor_sync(0xffffffffu, v1, off);
            int   ok1 = __shfl_xor_sync(0xffffffffu, k1, off);
            float ov2 = __shfl_xor_sync(0xffffffffu, v2, off);
            int   ok2 = __shfl_xor_sync(0xffffffffu, k2, off);
            merge_top2(v1, k1, v2, k2, ov1, ok1, ov2, ok2);
        }
        int widx = k1;
        bool need = (v2 - v1 < MARGIN);
        if (__any_sync(0xffffffffu, need)) {
            float lim = v1 + MARGIN;
            float ev1 = FLT_MAX, ev2 = FLT_MAX;
            int   ek1 = 0x7fffffff, ek2 = 0x7fffffff;
            if (need) {
                const float4* xr = (const float4*)(x + (size_t)(m0 + gr) * DIMS);
                float cv[3] = { hv1[ri], hv2[ri], hv3[ri] };
                int   ck[3] = { hk1[ri], hk2[ri], hk3[ri] };
#pragma unroll
                for (int c = 0; c < 3; c++) {
                    if (cv[c] <= lim && ck[c] != 0x7fffffff) {
                        int kc = ck[c];
                        float s = exact_score(xr, kc, ens[kc]);
                        if (s < ev1 || (s == ev1 && kc < ek1)) {
                            ev2 = ev1; ek2 = ek1; ev1 = s; ek1 = kc;
                        } else if (s < ev2 || (s == ev2 && kc < ek2)) {
                            ev2 = s; ek2 = kc;
                        }
                    }
                }
            }
#pragma unroll
            for (int off = 1; off <= 2; off <<= 1) {
                float ov1 = __shfl_xor_sync(0xffffffffu, ev1, off);
                int   ok1 = __shfl_xor_sync(0xffffffffu, ek1, off);
                float ov2 = __shfl_xor_sync(0xffffffffu, ev2, off);
                int   ok2 = __shfl_xor_sync(0xffffffffu, ek2, off);
                merge_top2(ev1, ek1, ev2, ek2, ov1, ok1, ov2, ok2);
            }
            if (need) widx = ek1;
            bool tneed = need && (ek2 != 0x7fffffff) && (ev2 - ev1 < 3e-4f);
            if (__any_sync(0xffffffffu, tneed)) {
                int tw = widx;
                if (tneed && (L & 3) == 0) {
                    int ka = min(ek1, ek2), kb = max(ek1, ek2);
                    tw = vote_tie(x, m0 + gr, ka, kb);
                }
                int bw = __shfl_sync(0xffffffffu, tw, L & ~3);
                if (tneed) widx = bw;
            }
        }
        if ((L & 3) == 0) bidx[gr] = widx;
    }
    __syncthreads();

    // epilogue: out = x + (q - x), loss
    float lsum = 0.f;
    for (int m = 0; m < H_MBLK; m++) {
        int idx = bidx[m];
        float q  = g_eT[(size_t)idx * DIMS + tid];
        float xv = x[(size_t)(m0 + m) * DIMS + tid];
        out[(size_t)(m0 + m) * DIMS + tid] = __fadd_rn(xv, __fsub_rn(q, xv));
        float dq = __fsub_rn(q, xv);
        lsum = fmaf(dq, dq, lsum);
    }
#pragma unroll
    for (int off = 16; off; off >>= 1)
        lsum += __shfl_xor_sync(0xffffffffu, lsum, off);
    __shared__ float wsum[8];
    if (L == 0) wsum[w] = lsum;
    __syncthreads();
    if (tid == 0) {
        float t = 0.f;
#pragma unroll
        for (int q = 0; q < 8; q++) t += wsum[q];
        atomicAdd(&g_loss, (double)t);
    }
}

__global__ void finalize_kernel(float* __restrict__ out, long long loss_index) {
    if (threadIdx.x == 0) {
        float m = (float)(g_loss / (double)((long long)N_VEC * DIMS));
        out[loss_index] = __fadd_rn(__fmul_rn(0.25f, m), m);
    }
}

// ---------------------------------------------------------------------------
extern "C" void kernel_launch(void* const* d_in, const int* in_sizes, int n_in,
                              void* d_out, int out_size) {
    const float* x   = (const float*)d_in[0];
    const float* emb = (const float*)d_in[1];
    float* out = (float*)d_out;

    dim3 tb(32, 8);
    transpose_e_kernel<<<dim3(KCODES / 32, DIMS / 32), tb>>>(emb);
    enorm_kernel<<<KCODES / 8, 256>>>();
    convert_etb_kernel<<<128, 256>>>();

    cudaFuncSetAttribute(vq_hmma_kernel,
                         cudaFuncAttributeMaxDynamicSharedMemorySize, SMH_TOTAL);
    vq_hmma_kernel<<<N_VEC / H_MBLK, HT, SMH_TOTAL>>>(x, out);

    finalize_kernel<<<1, 32>>>(out, (long long)out_size - 1);
}

// round 8
// speedup vs baseline: 1.6231x; 1.6231x over previous
#include <cuda_runtime.h>
#include <cuda_bf16.h>
#include <cstdint>
#include <float.h>

#define N_VEC    32768
#define DIMS     256
#define KCODES   1024
#define MARGIN   0.05f

// -------- device scratch ----------------------------------------------------
__device__ __align__(16) float          g_eT[KCODES * DIMS];    // fp32 codes [K][D]
__device__ __align__(16) __nv_bfloat16  g_etb[KCODES * DIMS];   // bf16 codes [K][D]
__device__ float  g_enorm2[KCODES];
__device__ double g_loss;

// -------- common helpers ------------------------------------------------------
__device__ __forceinline__ uint32_t smem_u32(const void* p) {
    uint32_t a;
    asm("{ .reg .u64 t; cvta.to.shared.u64 t, %1; cvt.u32.u64 %0, t; }"
        : "=r"(a) : "l"(p));
    return a;
}
__device__ __forceinline__ unsigned pack_bf2(float a, float b) {
    __nv_bfloat162 h = __floats2bfloat162_rn(a, b);
    return *reinterpret_cast<unsigned*>(&h);
}
__device__ __forceinline__ bool better(float v, int k, float v2, int k2) {
    return (v < v2) || (v == v2 && k < k2);
}
__device__ __forceinline__ void merge_top2(float& v1, int& k1, float& v2, int& k2,
                                           float ov1, int ok1, float ov2, int ok2) {
    float m1v, m2v; int m1k, m2k;
    if (better(v1, k1, ov1, ok1)) {
        m1v = v1; m1k = k1;
        if (better(v2, k2, ov1, ok1)) { m2v = v2; m2k = k2; }
        else                          { m2v = ov1; m2k = ok1; }
    } else {
        m1v = ov1; m1k = ok1;
        if (better(ov2, ok2, v1, k1)) { m2v = ov2; m2k = ok2; }
        else                          { m2v = v1;  m2k = k1;  }
    }
    v1 = m1v; k1 = m1k; v2 = m2v; k2 = m2k;
}

// reference-rounding-emulation tie vote (identical to the rel_err=0 round-2 code)
__device__ int vote_tie(const float* __restrict__ x, int v, int ka, int kb) {
    const float* xr = x + (size_t)v * DIMS;
    const float* ea = g_eT + (size_t)ka * DIMS;
    const float* eb = g_eT + (size_t)kb * DIMS;
    double sA = 0.0, sBa = 0.0, sBb = 0.0;
    for (int d = 0; d < DIMS; d++) {
        double xv = (double)xr[d];
        sA  += xv * xv;
        sBa += xv * (double)ea[d];
        sBb += xv * (double)eb[d];
    }
    float Ba = (float)sBa, Bb = (float)sBb;
    float Ca = g_enorm2[ka], Cb = g_enorm2[kb];
    int ab = __float_as_int((float)sA);
    int votes = 0;
#pragma unroll
    for (int jj = -2; jj <= 2; jj++) {
        int w = 3 - (jj < 0 ? -jj : jj);
        float Aj = __int_as_float(ab + jj);
        float da = __fadd_rn(__fsub_rn(Aj, __fmul_rn(2.f, Ba)), Ca);
        float db = __fadd_rn(__fsub_rn(Aj, __fmul_rn(2.f, Bb)), Cb);
        if (da <= db) votes += w;
    }
    return (votes >= 5) ? ka : kb;
}

__device__ __forceinline__ float exact_score(const float4* xr, int k, float enk) {
    const float4* er = (const float4*)(g_eT + (size_t)k * DIMS);
    float a0 = 0.f, a1 = 0.f, a2 = 0.f, a3 = 0.f;
#pragma unroll 8
    for (int d4 = 0; d4 < DIMS / 4; d4++) {
        float4 xv = __ldg(xr + d4), ev = __ldg(er + d4);
        a0 = fmaf(xv.x, ev.x, a0); a1 = fmaf(xv.y, ev.y, a1);
        a2 = fmaf(xv.z, ev.z, a2); a3 = fmaf(xv.w, ev.w, a3);
    }
    return fmaf(-2.f, (a0 + a1) + (a2 + a3), enk);
}

// -------- pre-kernels ---------------------------------------------------------
__global__ void transpose_e_kernel(const float* __restrict__ e) {
    __shared__ float tile[32][33];
    int k0 = blockIdx.x * 32, d0 = blockIdx.y * 32;
    int tx = threadIdx.x, ty = threadIdx.y;
#pragma unroll
    for (int i = ty; i < 32; i += 8)
        tile[i][tx] = e[(size_t)(d0 + i) * KCODES + k0 + tx];
    __syncthreads();
#pragma unroll
    for (int j = ty; j < 32; j += 8)
        g_eT[(size_t)(k0 + j) * DIMS + d0 + tx] = tile[tx][j];
}

__global__ void enorm_kernel() {
    int k = blockIdx.x * 8 + (threadIdx.x >> 5);
    int lane = threadIdx.x & 31;
    const float* row = g_eT + (size_t)k * DIMS;
    double s = 0.0;
#pragma unroll
    for (int j = 0; j < 8; j++) {
        double v = (double)row[lane + 32 * j];
        s += v * v;
    }
#pragma unroll
    for (int off = 16; off; off >>= 1)
        s += __shfl_xor_sync(0xffffffffu, s, off);
    if (lane == 0) g_enorm2[k] = (float)s;
    if (blockIdx.x == 0 && threadIdx.x == 0) g_loss = 0.0;
}

__global__ void convert_etb_kernel() {
    int i = blockIdx.x * 256 + threadIdx.x;
    const float4* s = (const float4*)g_eT;
    float4 f0 = s[i * 2], f1 = s[i * 2 + 1];
    uint4 d;
    d.x = pack_bf2(f0.x, f0.y); d.y = pack_bf2(f0.z, f0.w);
    d.z = pack_bf2(f1.x, f1.y); d.w = pack_bf2(f1.z, f1.w);
    ((uint4*)g_etb)[i] = d;
}

// ============================================================================
// HMMA (mma.sync bf16) main kernel — 16 warps, 8 mma chains per warp
// ============================================================================
#define HT        512
#define H_MBLK    256
#define H_NCH     64
#define H_NCHUNKS 16
#define H_RSTRIDE 528                 // padded row stride (bytes) = 264 bf16
#define SMH_ENS   0
#define SMH_BIDX  4096
#define SMH_A     5120
#define SMH_B     (SMH_A + 256 * H_RSTRIDE)       // 5120 + 135168 = 140288
#define H_BUFSZ   (64 * H_RSTRIDE)                // 33792
#define SMH_TOTAL (SMH_B + 2 * H_BUFSZ)           // 207872

__device__ __forceinline__ void cp16(uint32_t dst, const void* src) {
    asm volatile("cp.async.cg.shared.global [%0], [%1], 16;"
                 :: "r"(dst), "l"(src) : "memory");
}
#define CP_COMMIT() asm volatile("cp.async.commit_group;" ::: "memory")
#define CP_WAIT1()  asm volatile("cp.async.wait_group 1;" ::: "memory")

__device__ __forceinline__ void ldsm4(uint32_t* r, uint32_t addr) {
    asm volatile("ldmatrix.sync.aligned.m8n8.x4.shared.b16 {%0,%1,%2,%3}, [%4];"
                 : "=r"(r[0]), "=r"(r[1]), "=r"(r[2]), "=r"(r[3]) : "r"(addr));
}
__device__ __forceinline__ void mma16816(float* c, const uint32_t* a,
                                         uint32_t b0, uint32_t b1) {
    asm volatile("mma.sync.aligned.m16n8k16.row.col.f32.bf16.bf16.f32 "
                 "{%0,%1,%2,%3}, {%4,%5,%6,%7}, {%8,%9}, {%0,%1,%2,%3};"
                 : "+f"(c[0]), "+f"(c[1]), "+f"(c[2]), "+f"(c[3])
                 : "r"(a[0]), "r"(a[1]), "r"(a[2]), "r"(a[3]), "r"(b0), "r"(b1));
}

__global__ void __launch_bounds__(HT, 1)
vq_hmma_kernel(const float* __restrict__ x, float* __restrict__ out) {
    extern __shared__ char smem[];
    uint32_t sb = smem_u32(smem);
    float* ens = (float*)(smem + SMH_ENS);
    int*  bidx = (int*)(smem + SMH_BIDX);
    int tid = threadIdx.x, w = tid >> 5, L = tid & 31;
    int m0 = blockIdx.x * H_MBLK;

    for (int i = tid; i < KCODES; i += HT) ens[i] = g_enorm2[i];

    // A tile: x fp32 -> bf16, padded-stride smem [256][264 bf16]
    const float4* xs = (const float4*)x;
    for (int u = tid; u < 8192; u += HT) {
        int row = u >> 5, c = u & 31;
        size_t s4 = ((size_t)(m0 + row)) * 64 + c * 2;
        float4 f0 = __ldg(xs + s4), f1 = __ldg(xs + s4 + 1);
        uint4 d;
        d.x = pack_bf2(f0.x, f0.y); d.y = pack_bf2(f0.z, f0.w);
        d.z = pack_bf2(f1.x, f1.y); d.w = pack_bf2(f1.z, f1.w);
        *(uint4*)(smem + SMH_A + row * H_RSTRIDE + c * 16) = d;
    }
    // preload B chunk 0
    {
        const char* ebase = (const char*)g_etb;
        for (int u = tid; u < 2048; u += HT)
            cp16(sb + SMH_B + (u >> 5) * H_RSTRIDE + (u & 31) * 16,
                 ebase + (size_t)(u >> 5) * 512 + (u & 31) * 16);
        CP_COMMIT();
    }

    // lane-dependent ldmatrix address parts
    // A: warp owns rows [w*16, w*16+16): one m16 tile
    uint32_t a_lane = sb + SMH_A + (uint32_t)(w * 16 + (L & 15)) * H_RSTRIDE
                    + (uint32_t)(L >> 4) * 16;
    // B ldsm4: matrices = (ni, k0), (ni, k1), (ni+1, k0), (ni+1, k1)
    uint32_t b_lane = (uint32_t)(L & 7) * H_RSTRIDE + (uint32_t)((L >> 3) & 1) * 16
                    + (uint32_t)(L >> 4) * (8 * H_RSTRIDE);

    // per-lane running top-3 for 2 owned rows: w*16 + {0,8} + (L>>2)
    float hv1[2], hv2[2], hv3[2]; int hk1[2], hk2[2], hk3[2];
#pragma unroll
    for (int q = 0; q < 2; q++) {
        hv1[q] = FLT_MAX; hv2[q] = FLT_MAX; hv3[q] = FLT_MAX;
        hk1[q] = 0x7fffffff; hk2[q] = 0x7fffffff; hk3[q] = 0x7fffffff;
    }

#define UPD(ri, kk, vv) do {                                                    \
    float s_ = fmaf(-2.f, (vv), ens[(kk)]);                                     \
    if (s_ < hv3[ri]) {                                                         \
        if (s_ < hv1[ri]) {                                                     \
            hv3[ri] = hv2[ri]; hk3[ri] = hk2[ri];                               \
            hv2[ri] = hv1[ri]; hk2[ri] = hk1[ri];                               \
            hv1[ri] = s_; hk1[ri] = (kk);                                       \
        } else if (s_ < hv2[ri]) {                                              \
            hv3[ri] = hv2[ri]; hk3[ri] = hk2[ri];                               \
            hv2[ri] = s_; hk2[ri] = (kk);                                       \
        } else { hv3[ri] = s_; hk3[ri] = (kk); }                                \
    } } while (0)

    for (int i = 0; i < H_NCHUNKS; i++) {
        if (i + 1 < H_NCHUNKS) {
            const char* ebase = (const char*)g_etb + (size_t)(i + 1) * H_NCH * 512;
            uint32_t bdst = sb + SMH_B + ((i + 1) & 1) * H_BUFSZ;
            for (int u = tid; u < 2048; u += HT)
                cp16(bdst + (u >> 5) * H_RSTRIDE + (u & 31) * 16,
                     ebase + (size_t)(u >> 5) * 512 + (u & 31) * 16);
        }
        CP_COMMIT();
        CP_WAIT1();
        __syncthreads();                       // chunk i visible; A on i==0

        uint32_t bbase = sb + SMH_B + (i & 1) * H_BUFSZ + b_lane;

        float acc[8][4];                       // 8 independent mma chains
#pragma unroll
        for (int ni = 0; ni < 8; ni++)
#pragma unroll
            for (int c = 0; c < 4; c++) acc[ni][c] = 0.f;

#pragma unroll 4
        for (int ks = 0; ks < 16; ks++) {
            uint32_t af[4];
            ldsm4(af, a_lane + ks * 32);
#pragma unroll
            for (int p = 0; p < 4; p++) {
                uint32_t bf[4];
                ldsm4(bf, bbase + p * (16 * H_RSTRIDE) + ks * 32);
                mma16816(acc[2 * p],     af, bf[0], bf[1]);
                mma16816(acc[2 * p + 1], af, bf[2], bf[3]);
            }
        }

        int kb_base = i * H_NCH + (L & 3) * 2;
#pragma unroll
        for (int ni = 0; ni < 8; ni++) {
            int kb = kb_base + ni * 8;
            UPD(0, kb, acc[ni][0]); UPD(0, kb + 1, acc[ni][1]);
            UPD(1, kb, acc[ni][2]); UPD(1, kb + 1, acc[ni][3]);
        }
        __syncthreads();                       // readers done before buf reuse
    }
#undef UPD

    // per-row decision: quad merge -> margin -> exact rescore -> tie vote
#pragma unroll 1
    for (int ri = 0; ri < 2; ri++) {
        int gr = w * 16 + ri * 8 + (L >> 2);
        float v1 = hv1[ri], v2 = hv2[ri];
        int   k1 = hk1[ri], k2 = hk2[ri];
#pragma unroll
        for (int off = 1; off <= 2; off <<= 1) {
            float ov1 = __shfl_xor_sync(0xffffffffu, v1, off);
            int   ok1 = __shfl_xor_sync(0xffffffffu, k1, off);
            float ov2 = __shfl_xor_sync(0xffffffffu, v2, off);
            int   ok2 = __shfl_xor_sync(0xffffffffu, k2, off);
            merge_top2(v1, k1, v2, k2, ov1, ok1, ov2, ok2);
        }
        int widx = k1;
        bool need = (v2 - v1 < MARGIN);
        if (__any_sync(0xffffffffu, need)) {
            float lim = v1 + MARGIN;
            float ev1 = FLT_MAX, ev2 = FLT_MAX;
            int   ek1 = 0x7fffffff, ek2 = 0x7fffffff;
            if (need) {
                const float4* xr = (const float4*)(x + (size_t)(m0 + gr) * DIMS);
                float cv[3] = { hv1[ri], hv2[ri], hv3[ri] };
                int   ck[3] = { hk1[ri], hk2[ri], hk3[ri] };
#pragma unroll
                for (int c = 0; c < 3; c++) {
                    if (cv[c] <= lim && ck[c] != 0x7fffffff) {
                        int kc = ck[c];
                        float s = exact_score(xr, kc, ens[kc]);
                        if (s < ev1 || (s == ev1 && kc < ek1)) {
                            ev2 = ev1; ek2 = ek1; ev1 = s; ek1 = kc;
                        } else if (s < ev2 || (s == ev2 && kc < ek2)) {
                            ev2 = s; ek2 = kc;
                        }
                    }
                }
            }
#pragma unroll
            for (int off = 1; off <= 2; off <<= 1) {
                float ov1 = __shfl_xor_sync(0xffffffffu, ev1, off);
                int   ok1 = __shfl_xor_sync(0xffffffffu, ek1, off);
                float ov2 = __shfl_xor_sync(0xffffffffu, ev2, off);
                int   ok2 = __shfl_xor_sync(0xffffffffu, ek2, off);
                merge_top2(ev1, ek1, ev2, ek2, ov1, ok1, ov2, ok2);
            }
            if (need) widx = ek1;
            bool tneed = need && (ek2 != 0x7fffffff) && (ev2 - ev1 < 3e-4f);
            if (__any_sync(0xffffffffu, tneed)) {
                int tw = widx;
                if (tneed && (L & 3) == 0) {
                    int ka = min(ek1, ek2), kb = max(ek1, ek2);
                    tw = vote_tie(x, m0 + gr, ka, kb);
                }
                int bw = __shfl_sync(0xffffffffu, tw, L & ~3);
                if (tneed) widx = bw;
            }
        }
        if ((L & 3) == 0) bidx[gr] = widx;
    }
    __syncthreads();

    // epilogue: out = x + (q - x), loss  (512 threads: 2 rows per iteration)
    float lsum = 0.f;
    int d = tid & 255;
    for (int m = tid >> 8; m < H_MBLK; m += 2) {
        int idx = bidx[m];
        float q  = g_eT[(size_t)idx * DIMS + d];
        float xv = x[(size_t)(m0 + m) * DIMS + d];
        out[(size_t)(m0 + m) * DIMS + d] = __fadd_rn(xv, __fsub_rn(q, xv));
        float dq = __fsub_rn(q, xv);
        lsum = fmaf(dq, dq, lsum);
    }
#pragma unroll
    for (int off = 16; off; off >>= 1)
        lsum += __shfl_xor_sync(0xffffffffu, lsum, off);
    __shared__ float wsum[16];
    if (L == 0) wsum[w] = lsum;
    __syncthreads();
    if (tid == 0) {
        float t = 0.f;
#pragma unroll
        for (int q = 0; q < 16; q++) t += wsum[q];
        atomicAdd(&g_loss, (double)t);
    }
}

__global__ void finalize_kernel(float* __restrict__ out, long long loss_index) {
    if (threadIdx.x == 0) {
        float m = (float)(g_loss / (double)((long long)N_VEC * DIMS));
        out[loss_index] = __fadd_rn(__fmul_rn(0.25f, m), m);
    }
}

// ---------------------------------------------------------------------------
extern "C" void kernel_launch(void* const* d_in, const int* in_sizes, int n_in,
                              void* d_out, int out_size) {
    const float* x   = (const float*)d_in[0];
    const float* emb = (const float*)d_in[1];
    float* out = (float*)d_out;

    dim3 tb(32, 8);
    transpose_e_kernel<<<dim3(KCODES / 32, DIMS / 32), tb>>>(emb);
    enorm_kernel<<<KCODES / 8, 256>>>();
    convert_etb_kernel<<<128, 256>>>();

    cudaFuncSetAttribute(vq_hmma_kernel,
                         cudaFuncAttributeMaxDynamicSharedMemorySize, SMH_TOTAL);
    vq_hmma_kernel<<<N_VEC / H_MBLK, HT, SMH_TOTAL>>>(x, out);

    finalize_kernel<<<1, 32>>>(out, (long long)out_size - 1);
}